// round 4
// baseline (speedup 1.0000x reference)
#include <cuda_runtime.h>
#include <cstdint>

#define D_DIM  448
#define MTOT   32768
#define BM     128
#define BN     112
#define BK     32
#define NSTG   2
#define A_STRIDE 36                       // floats per smem row (32 + 4 pad)
#define AS_F   (BM * A_STRIDE)            // 4608 floats
#define BS_F   (BN * A_STRIDE)            // 4032 floats
#define STG_F  (AS_F + BS_F)              // 8640 floats per stage
#define SMEM_BYTES (NSTG * STG_F * 4)     // 69120 -> 3 CTAs/SM

// W_eff, transposed [n][k_permuted], tf32-rounded fp32.
// k permutation within each 8-block: logical j -> pos (j<4 ? 2j : 2(j-4)+1),
// so the mma B-fragment pair (t, t+4) sits at adjacent floats -> ld.shared.v2.
__device__ __align__(16) float g_W[D_DIM * D_DIM];

// ---- helpers ----------------------------------------------------------------
__device__ __forceinline__ uint32_t smem_u32(const void* p) {
    uint32_t a;
    asm("{ .reg .u64 t; cvta.to.shared.u64 t, %1; cvt.u32.u64 %0, t; }" : "=r"(a) : "l"(p));
    return a;
}
__device__ __forceinline__ uint32_t f2tf32(float f) {
    uint32_t r;
    asm("cvt.rna.tf32.f32 %0, %1;" : "=r"(r) : "f"(f));
    return r;
}
__device__ __forceinline__ void mma_tf32(float* c, const uint32_t* a, uint32_t b0, uint32_t b1) {
    asm volatile(
        "mma.sync.aligned.m16n8k8.row.col.f32.tf32.tf32.f32 "
        "{%0,%1,%2,%3}, {%4,%5,%6,%7}, {%8,%9}, {%0,%1,%2,%3};"
        : "+f"(c[0]), "+f"(c[1]), "+f"(c[2]), "+f"(c[3])
        : "r"(a[0]), "r"(a[1]), "r"(a[2]), "r"(a[3]), "r"(b0), "r"(b1));
}
#define CP16(dst, src) \
    asm volatile("cp.async.cg.shared.global [%0], [%1], 16;" :: "r"(dst), "l"(src) : "memory")
#define CP_COMMIT() asm volatile("cp.async.commit_group;" ::: "memory")
#define CP_WAIT1()  asm volatile("cp.async.wait_group 1;" ::: "memory")

// ---------------------------------------------------------------------------
// Kernel 1: W_eff[k][n] = sum_d (Wq[k][d]*a[d]+Wk[k][d]*b[d]+Wv[k][d]*c[d]) * Wo[d][n]
// Diagonals staged in smem once. Output transposed + k-permuted + tf32-rounded.
// ---------------------------------------------------------------------------
__global__ void build_weff_kernel(const float* __restrict__ Wq, const float* __restrict__ Wk,
                                  const float* __restrict__ Wv, const float* __restrict__ Wo,
                                  const float* __restrict__ A,  const float* __restrict__ Bm,
                                  const float* __restrict__ C) {
    __shared__ float dA[D_DIM], dB[D_DIM], dC[D_DIM];
    __shared__ float Ms[16][17];
    __shared__ float Ws[16][17];
    const int ty = threadIdx.y, tx = threadIdx.x;
    const int tid = ty * 16 + tx;
    for (int i = tid; i < D_DIM; i += 256) {
        dA[i] = A[(size_t)i * D_DIM + i];
        dB[i] = Bm[(size_t)i * D_DIM + i];
        dC[i] = C[(size_t)i * D_DIM + i];
    }
    __syncthreads();

    const int row = blockIdx.y * 16 + ty;   // k index
    const int col = blockIdx.x * 16 + tx;   // n index
    float acc = 0.f;
    for (int kt = 0; kt < D_DIM; kt += 16) {
        const int k = kt + tx;
        Ms[ty][tx] = Wq[row * D_DIM + k] * dA[k] + Wk[row * D_DIM + k] * dB[k]
                   + Wv[row * D_DIM + k] * dC[k];
        Ws[ty][tx] = Wo[(kt + ty) * D_DIM + col];
        __syncthreads();
#pragma unroll
        for (int kk = 0; kk < 16; kk++)
            acc += Ms[ty][kk] * Ws[kk][tx];
        __syncthreads();
    }
    const int j = row & 7;
    const int rp = (row & ~7) | (j < 4 ? 2 * j : 2 * (j - 4) + 1);
    g_W[col * D_DIM + rp] = __uint_as_float(f2tf32(acc));
}

// ---------------------------------------------------------------------------
// Kernel 2: out = x @ W_eff via tf32 mma.sync.
// BM=128, BN=112, BK=32, 2-stage cp.async double buffer, 256 threads
// (8 warps, 4m x 2n), warp tile 32x56. 3 CTAs/SM.
// ---------------------------------------------------------------------------
__global__ void __launch_bounds__(256, 3) gemm_tf32_kernel(const float* __restrict__ x,
                                                           float* __restrict__ out) {
    extern __shared__ __align__(16) float smem[];

    const int tid   = threadIdx.x;
    const int wid   = tid >> 5;
    const int lane  = tid & 31;
    const int g     = lane >> 2;   // 0..7
    const int t     = lane & 3;    // 0..3
    const int warpM = wid & 3;     // m offset 32*warpM
    const int warpN = wid >> 2;    // n offset 56*warpN

    const int m0 = blockIdx.y * BM;
    const int n0 = blockIdx.x * BN;

    const uint32_t smem_base = smem_u32(smem);

    float acc[2][7][4];
#pragma unroll
    for (int i = 0; i < 2; i++)
#pragma unroll
        for (int j = 0; j < 7; j++)
#pragma unroll
            for (int q = 0; q < 4; q++) acc[i][j][q] = 0.f;

    // ---- stage loader: A tile 128x32 fp32 (raw x), B tile 112x32 (permuted g_W)
    auto load_stage = [&](int s, int kt) {
        const uint32_t aBase = smem_base + (uint32_t)(s * STG_F) * 4u;
        const uint32_t bBase = aBase + (uint32_t)AS_F * 4u;
#pragma unroll
        for (int j = 0; j < 4; j++) {
            const int id  = tid + j * 256;
            const int row = id >> 3;
            const int c   = id & 7;
            CP16(aBase + (uint32_t)(row * A_STRIDE + c * 4) * 4u,
                 x + (size_t)(m0 + row) * D_DIM + kt + c * 4);
        }
#pragma unroll
        for (int j = 0; j < 3; j++) {
            const int id  = tid + j * 256;
            const int row = id >> 3;
            const int c   = id & 7;
            CP16(bBase + (uint32_t)(row * A_STRIDE + c * 4) * 4u,
                 g_W + (size_t)(n0 + row) * D_DIM + kt + c * 4);
        }
        if (tid < 128) {
            const int id  = tid + 768;
            const int row = id >> 3;
            const int c   = id & 7;
            CP16(bBase + (uint32_t)(row * A_STRIDE + c * 4) * 4u,
                 g_W + (size_t)(n0 + row) * D_DIM + kt + c * 4);
        }
    };

    load_stage(0, 0);
    CP_COMMIT();
    load_stage(1, BK);
    CP_COMMIT();

    const int NIT = D_DIM / BK;   // 14
#pragma unroll 1
    for (int it = 0; it < NIT; it++) {
        CP_WAIT1();
        __syncthreads();

        const float* As = smem + (it & 1) * STG_F;
        const float* Bs = As + AS_F;
        const float* Arow = As + (warpM * 32 + g) * A_STRIDE;
        const float* Brow = Bs + (warpN * 56 + g) * A_STRIDE;

#pragma unroll
        for (int kk = 0; kk < 4; kk++) {
            const int k0 = kk * 8;
            uint32_t af[2][4];
#pragma unroll
            for (int mi = 0; mi < 2; mi++) {
                const float* Ar = Arow + mi * 16 * A_STRIDE;
                af[mi][0] = f2tf32(Ar[k0 + t]);
                af[mi][1] = f2tf32(Ar[8 * A_STRIDE + k0 + t]);
                af[mi][2] = f2tf32(Ar[k0 + t + 4]);
                af[mi][3] = f2tf32(Ar[8 * A_STRIDE + k0 + t + 4]);
            }
#pragma unroll
            for (int ni = 0; ni < 7; ni++) {
                // permuted layout: logical (k0+t, k0+t+4) at floats (k0+2t, k0+2t+1)
                const float2 bv = *reinterpret_cast<const float2*>(
                    Brow + ni * 8 * A_STRIDE + k0 + 2 * t);
                const uint32_t b0 = __float_as_uint(bv.x);
                const uint32_t b1 = __float_as_uint(bv.y);
                mma_tf32(acc[0][ni], af[0], b0, b1);
                mma_tf32(acc[1][ni], af[1], b0, b1);
            }
        }
        __syncthreads();

        // prefetch it+2 into the slot just freed (slot it&1)
        if (it + 2 < NIT) load_stage(it & 1, (it + 2) * BK);
        CP_COMMIT();   // unconditional: keeps wait_group accounting exact
    }

    // ---- epilogue: rows (g, g+8), cols (2t, 2t+1) per (mi, ni)
#pragma unroll
    for (int mi = 0; mi < 2; mi++) {
        const int r0 = m0 + warpM * 32 + mi * 16 + g;
#pragma unroll
        for (int ni = 0; ni < 7; ni++) {
            const int c0 = n0 + warpN * 56 + ni * 8 + 2 * t;
            float2 v0, v1;
            v0.x = acc[mi][ni][0]; v0.y = acc[mi][ni][1];
            v1.x = acc[mi][ni][2]; v1.y = acc[mi][ni][3];
            *reinterpret_cast<float2*>(out + (size_t)r0 * D_DIM + c0)       = v0;
            *reinterpret_cast<float2*>(out + (size_t)(r0 + 8) * D_DIM + c0) = v1;
        }
    }
}

// ---------------------------------------------------------------------------
extern "C" void kernel_launch(void* const* d_in, const int* in_sizes, int n_in,
                              void* d_out, int out_size) {
    const float* x  = (const float*)d_in[0];
    const float* Wq = (const float*)d_in[1];
    const float* Wk = (const float*)d_in[2];
    const float* Wv = (const float*)d_in[3];
    const float* Wo = (const float*)d_in[4];
    const float* A  = (const float*)d_in[5];
    const float* B  = (const float*)d_in[6];
    const float* C  = (const float*)d_in[7];

    cudaFuncSetAttribute(gemm_tf32_kernel, cudaFuncAttributeMaxDynamicSharedMemorySize,
                         SMEM_BYTES);

    build_weff_kernel<<<dim3(D_DIM / 16, D_DIM / 16), dim3(16, 16)>>>(Wq, Wk, Wv, Wo, A, B, C);
    gemm_tf32_kernel<<<dim3(D_DIM / BN, MTOT / BM), 256, SMEM_BYTES>>>(x, (float*)d_out);
}

// round 5
// speedup vs baseline: 1.0445x; 1.0445x over previous
#include <cuda_runtime.h>
#include <cstdint>

#define D_DIM  448
#define MTOT   32768
#define BM     128
#define BN     112
#define BK     32
#define NSTG   3
#define A_STRIDE 36
#define AS_F   (BM * A_STRIDE)
#define BS_F   (BN * A_STRIDE)
#define STG_F  (AS_F + BS_F)
#define SMEM_BYTES (NSTG * STG_F * 4)     // 103680 -> 2 CTAs/SM

// W_eff transposed [n][k_perm], tf32-rounded. perm within 8-block: j<4 ? 2j : 2(j-4)+1
__device__ __align__(16) float g_W[D_DIM * D_DIM];
__device__ __align__(16) float g_Wmid[D_DIM * D_DIM];
__device__ __align__(16) float g_diag[3 * D_DIM];

// ---- helpers ----------------------------------------------------------------
__device__ __forceinline__ uint32_t smem_u32(const void* p) {
    uint32_t a;
    asm("{ .reg .u64 t; cvta.to.shared.u64 t, %1; cvt.u32.u64 %0, t; }" : "=r"(a) : "l"(p));
    return a;
}
__device__ __forceinline__ uint32_t f2tf32(float f) {
    uint32_t r;
    asm("cvt.rna.tf32.f32 %0, %1;" : "=r"(r) : "f"(f));
    return r;
}
__device__ __forceinline__ void mma_tf32(float* c, const uint32_t* a, uint32_t b0, uint32_t b1) {
    asm volatile(
        "mma.sync.aligned.m16n8k8.row.col.f32.tf32.tf32.f32 "
        "{%0,%1,%2,%3}, {%4,%5,%6,%7}, {%8,%9}, {%0,%1,%2,%3};"
        : "+f"(c[0]), "+f"(c[1]), "+f"(c[2]), "+f"(c[3])
        : "r"(a[0]), "r"(a[1]), "r"(a[2]), "r"(a[3]), "r"(b0), "r"(b1));
}
#define CP16(dst, src) \
    asm volatile("cp.async.cg.shared.global [%0], [%1], 16;" :: "r"(dst), "l"(src) : "memory")
#define CP_COMMIT() asm volatile("cp.async.commit_group;" ::: "memory")
#define CP_WAIT1()  asm volatile("cp.async.wait_group 1;" ::: "memory")

// ---------------------------------------------------------------------------
// Prep 1: extract diagonals (1 block, 448 threads)
// ---------------------------------------------------------------------------
__global__ void diag_kernel(const float* __restrict__ A, const float* __restrict__ Bm,
                            const float* __restrict__ C) {
    const int i = threadIdx.x;
    g_diag[i]             = A[(size_t)i * D_DIM + i];
    g_diag[D_DIM + i]     = Bm[(size_t)i * D_DIM + i];
    g_diag[2 * D_DIM + i] = C[(size_t)i * D_DIM + i];
}

// ---------------------------------------------------------------------------
// Prep 2: W_mid[k][d] = Wq*a + Wk*b + Wv*c   (float4 elementwise)
// ---------------------------------------------------------------------------
__global__ void __launch_bounds__(256) wmid_kernel(const float* __restrict__ Wq,
                                                   const float* __restrict__ Wk,
                                                   const float* __restrict__ Wv) {
    const int idx = blockIdx.x * 256 + threadIdx.x;        // 0 .. 50175 float4s
    const int d4  = (idx % (D_DIM / 4)) * 4;
    const float4 q = *reinterpret_cast<const float4*>(Wq + (size_t)idx * 4);
    const float4 k = *reinterpret_cast<const float4*>(Wk + (size_t)idx * 4);
    const float4 v = *reinterpret_cast<const float4*>(Wv + (size_t)idx * 4);
    const float4 a = *reinterpret_cast<const float4*>(g_diag + d4);
    const float4 b = *reinterpret_cast<const float4*>(g_diag + D_DIM + d4);
    const float4 c = *reinterpret_cast<const float4*>(g_diag + 2 * D_DIM + d4);
    float4 o;
    o.x = q.x * a.x + k.x * b.x + v.x * c.x;
    o.y = q.y * a.y + k.y * b.y + v.y * c.y;
    o.z = q.z * a.z + k.z * b.z + v.z * c.z;
    o.w = q.w * a.w + k.w * b.w + v.w * c.w;
    *reinterpret_cast<float4*>(g_Wmid + (size_t)idx * 4) = o;
}

// ---------------------------------------------------------------------------
// Prep 3: W_eff = W_mid @ Wo, written transposed + k-permuted + tf32 into g_W.
// BM=BN=64, BK=16, grid (7,7), 256 threads, 4x4 per thread.
// ---------------------------------------------------------------------------
__global__ void __launch_bounds__(256) weff_gemm_kernel(const float* __restrict__ Wo) {
    __shared__ float As[16][68];   // [d][k], transposed on store
    __shared__ float Bs[16][68];   // [d][n]
    const int tid = threadIdx.x;
    const int ty  = tid >> 4, tx = tid & 15;
    const int k0  = blockIdx.y * 64;
    const int n0  = blockIdx.x * 64;

    float acc[4][4] = {};
    for (int kt = 0; kt < D_DIM; kt += 16) {
        {
            const int kl = tid >> 2;
            const int d4 = (tid & 3) * 4;
            const float4 v = *reinterpret_cast<const float4*>(
                g_Wmid + (size_t)(k0 + kl) * D_DIM + kt + d4);
            As[d4 + 0][kl] = v.x; As[d4 + 1][kl] = v.y;
            As[d4 + 2][kl] = v.z; As[d4 + 3][kl] = v.w;
        }
        {
            const int row = tid >> 4;
            const int c4  = (tid & 15) * 4;
            *reinterpret_cast<float4*>(&Bs[row][c4]) = *reinterpret_cast<const float4*>(
                Wo + (size_t)(kt + row) * D_DIM + n0 + c4);
        }
        __syncthreads();
#pragma unroll
        for (int kk = 0; kk < 16; kk++) {
            float a[4], b[4];
#pragma unroll
            for (int i = 0; i < 4; i++) a[i] = As[kk][ty * 4 + i];
#pragma unroll
            for (int j = 0; j < 4; j++) b[j] = Bs[kk][tx * 4 + j];
#pragma unroll
            for (int i = 0; i < 4; i++)
#pragma unroll
                for (int j = 0; j < 4; j++) acc[i][j] += a[i] * b[j];
        }
        __syncthreads();
    }
#pragma unroll
    for (int i = 0; i < 4; i++) {
        const int k = k0 + ty * 4 + i;
        const int j = k & 7;
        const int kp = (k & ~7) | (j < 4 ? 2 * j : 2 * (j - 4) + 1);
#pragma unroll
        for (int jj = 0; jj < 4; jj++) {
            const int n = n0 + tx * 4 + jj;
            g_W[(size_t)n * D_DIM + kp] = __uint_as_float(f2tf32(acc[i][jj]));
        }
    }
}

// ---------------------------------------------------------------------------
// Main GEMM: out = x @ W_eff, tf32 mma.sync.
// BM=128, BN=112, BK=32, 3-stage cp.async, 256 threads (4m x 2n warps),
// warp tile 32x56, register double-buffered fragments.
// ---------------------------------------------------------------------------
__global__ void __launch_bounds__(256, 2) gemm_tf32_kernel(const float* __restrict__ x,
                                                           float* __restrict__ out) {
    extern __shared__ __align__(16) float smem[];

    const int tid   = threadIdx.x;
    const int wid   = tid >> 5;
    const int lane  = tid & 31;
    const int g     = lane >> 2;
    const int t     = lane & 3;
    const int warpM = wid & 3;
    const int warpN = wid >> 2;

    const int m0 = blockIdx.y * BM;
    const int n0 = blockIdx.x * BN;

    const uint32_t smem_base = smem_u32(smem);

    float acc[2][7][4];
#pragma unroll
    for (int i = 0; i < 2; i++)
#pragma unroll
        for (int j = 0; j < 7; j++)
#pragma unroll
            for (int q = 0; q < 4; q++) acc[i][j][q] = 0.f;

    auto load_stage = [&](int s, int kt) {
        const uint32_t aBase = smem_base + (uint32_t)(s * STG_F) * 4u;
        const uint32_t bBase = aBase + (uint32_t)AS_F * 4u;
#pragma unroll
        for (int j = 0; j < 4; j++) {
            const int id  = tid + j * 256;
            const int row = id >> 3;
            const int c   = id & 7;
            CP16(aBase + (uint32_t)(row * A_STRIDE + c * 4) * 4u,
                 x + (size_t)(m0 + row) * D_DIM + kt + c * 4);
        }
#pragma unroll
        for (int j = 0; j < 3; j++) {
            const int id  = tid + j * 256;
            const int row = id >> 3;
            const int c   = id & 7;
            CP16(bBase + (uint32_t)(row * A_STRIDE + c * 4) * 4u,
                 g_W + (size_t)(n0 + row) * D_DIM + kt + c * 4);
        }
        if (tid < 128) {
            const int id  = tid + 768;
            const int row = id >> 3;
            const int c   = id & 7;
            CP16(bBase + (uint32_t)(row * A_STRIDE + c * 4) * 4u,
                 g_W + (size_t)(n0 + row) * D_DIM + kt + c * 4);
        }
    };

    load_stage(0, 0);
    CP_COMMIT();
    load_stage(1, BK);
    CP_COMMIT();

    const int NIT = D_DIM / BK;   // 14
#pragma unroll 1
    for (int it = 0; it < NIT; it++) {
        CP_WAIT1();
        __syncthreads();

        // prefetch it+2 FIRST (deep overlap), then compute
        if (it + 2 < NIT) load_stage((it + 2) % NSTG, (it + 2) * BK);
        CP_COMMIT();

        const float* As = smem + (it % NSTG) * STG_F;
        const float* Bs = As + AS_F;
        const float* Arow = As + (warpM * 32 + g) * A_STRIDE;
        const float* Brow = Bs + (warpN * 56 + g) * A_STRIDE;

        uint32_t af[2][2][4];
        uint32_t bf[2][7][2];

        auto load_frags = [&](int kk, uint32_t a_[2][4], uint32_t b_[7][2]) {
            const int k0 = kk * 8;
#pragma unroll
            for (int mi = 0; mi < 2; mi++) {
                const float* Ar = Arow + mi * 16 * A_STRIDE;
                a_[mi][0] = f2tf32(Ar[k0 + t]);
                a_[mi][1] = f2tf32(Ar[8 * A_STRIDE + k0 + t]);
                a_[mi][2] = f2tf32(Ar[k0 + t + 4]);
                a_[mi][3] = f2tf32(Ar[8 * A_STRIDE + k0 + t + 4]);
            }
#pragma unroll
            for (int ni = 0; ni < 7; ni++) {
                const float2 bv = *reinterpret_cast<const float2*>(
                    Brow + ni * 8 * A_STRIDE + k0 + 2 * t);
                b_[ni][0] = __float_as_uint(bv.x);
                b_[ni][1] = __float_as_uint(bv.y);
            }
        };

        load_frags(0, af[0], bf[0]);
#pragma unroll
        for (int kk = 0; kk < 4; kk++) {
            const int cur = kk & 1;
            if (kk < 3) load_frags(kk + 1, af[cur ^ 1], bf[cur ^ 1]);
#pragma unroll
            for (int ni = 0; ni < 7; ni++) {
                mma_tf32(acc[0][ni], af[cur][0], bf[cur][ni][0], bf[cur][ni][1]);
                mma_tf32(acc[1][ni], af[cur][1], bf[cur][ni][0], bf[cur][ni][1]);
            }
        }
        __syncthreads();
    }

    // ---- epilogue
#pragma unroll
    for (int mi = 0; mi < 2; mi++) {
        const int r0 = m0 + warpM * 32 + mi * 16 + g;
#pragma unroll
        for (int ni = 0; ni < 7; ni++) {
            const int c0 = n0 + warpN * 56 + ni * 8 + 2 * t;
            float2 v0, v1;
            v0.x = acc[mi][ni][0]; v0.y = acc[mi][ni][1];
            v1.x = acc[mi][ni][2]; v1.y = acc[mi][ni][3];
            *reinterpret_cast<float2*>(out + (size_t)r0 * D_DIM + c0)       = v0;
            *reinterpret_cast<float2*>(out + (size_t)(r0 + 8) * D_DIM + c0) = v1;
        }
    }
}

// ---------------------------------------------------------------------------
extern "C" void kernel_launch(void* const* d_in, const int* in_sizes, int n_in,
                              void* d_out, int out_size) {
    const float* x  = (const float*)d_in[0];
    const float* Wq = (const float*)d_in[1];
    const float* Wk = (const float*)d_in[2];
    const float* Wv = (const float*)d_in[3];
    const float* Wo = (const float*)d_in[4];
    const float* A  = (const float*)d_in[5];
    const float* B  = (const float*)d_in[6];
    const float* C  = (const float*)d_in[7];

    cudaFuncSetAttribute(gemm_tf32_kernel, cudaFuncAttributeMaxDynamicSharedMemorySize,
                         SMEM_BYTES);

    diag_kernel<<<1, D_DIM>>>(A, B, C);
    wmid_kernel<<<(D_DIM * D_DIM / 4) / 256, 256>>>(Wq, Wk, Wv);
    weff_gemm_kernel<<<dim3(D_DIM / 64, D_DIM / 64), 256>>>(Wo);
    gemm_tf32_kernel<<<dim3(D_DIM / BN, MTOT / BM), 256, SMEM_BYTES>>>(x, (float*)d_out);
}

// round 6
// speedup vs baseline: 1.1987x; 1.1476x over previous
#include <cuda_runtime.h>
#include <cstdint>

#define D_DIM  448
#define MTOT   32768
#define BM     128
#define BN     112
#define BK     32
#define NSTG   3
#define A_STRIDE 36                        // conflict-free for scalar frag LDS
#define B_STRIDE 40                        // conflict-free for v2 frag LDS
#define AS_F   (BM * A_STRIDE)             // 4608
#define BS_F   (BN * B_STRIDE)             // 4480
#define STG_F  (AS_F + BS_F)               // 9088
#define SMEM_BYTES (NSTG * STG_F * 4)      // 109056 -> 2 CTAs/SM

// W_eff transposed [n][k_perm], tf32-rounded. perm in 8-block: j<4 ? 2j : 2(j-4)+1
__device__ __align__(16) float g_W[D_DIM * D_DIM];
__device__ __align__(16) float g_diag[3 * D_DIM];

// ---- helpers ----------------------------------------------------------------
__device__ __forceinline__ uint32_t smem_u32(const void* p) {
    uint32_t a;
    asm("{ .reg .u64 t; cvta.to.shared.u64 t, %1; cvt.u32.u64 %0, t; }" : "=r"(a) : "l"(p));
    return a;
}
__device__ __forceinline__ uint32_t f2tf32(float f) {
    uint32_t r;
    asm("cvt.rna.tf32.f32 %0, %1;" : "=r"(r) : "f"(f));
    return r;
}
__device__ __forceinline__ void mma_tf32(float* c, const uint32_t* a, uint32_t b0, uint32_t b1) {
    asm volatile(
        "mma.sync.aligned.m16n8k8.row.col.f32.tf32.tf32.f32 "
        "{%0,%1,%2,%3}, {%4,%5,%6,%7}, {%8,%9}, {%0,%1,%2,%3};"
        : "+f"(c[0]), "+f"(c[1]), "+f"(c[2]), "+f"(c[3])
        : "r"(a[0]), "r"(a[1]), "r"(a[2]), "r"(a[3]), "r"(b0), "r"(b1));
}
#define CP16(dst, src) \
    asm volatile("cp.async.cg.shared.global [%0], [%1], 16;" :: "r"(dst), "l"(src) : "memory")
#define CP_COMMIT() asm volatile("cp.async.commit_group;" ::: "memory")
#define CP_WAIT1()  asm volatile("cp.async.wait_group 1;" ::: "memory")

// ---------------------------------------------------------------------------
// Prep 1: extract diagonals (1 block, 448 threads)
// ---------------------------------------------------------------------------
__global__ void diag_kernel(const float* __restrict__ A, const float* __restrict__ Bm,
                            const float* __restrict__ C) {
    const int i = threadIdx.x;
    g_diag[i]             = A[(size_t)i * D_DIM + i];
    g_diag[D_DIM + i]     = Bm[(size_t)i * D_DIM + i];
    g_diag[2 * D_DIM + i] = C[(size_t)i * D_DIM + i];
}

// ---------------------------------------------------------------------------
// Prep 2 (fused): W_eff = (Wq*a + Wk*b + Wv*c) @ Wo, transposed + k-permuted +
// tf32 into g_W.  32x32 tiles, grid (14,14), 256 threads, 2x2 per thread.
// ---------------------------------------------------------------------------
__global__ void __launch_bounds__(256) weff_kernel(const float* __restrict__ Wq,
                                                   const float* __restrict__ Wk,
                                                   const float* __restrict__ Wv,
                                                   const float* __restrict__ Wo) {
    __shared__ float Ms[32][33];   // [k-row][d]
    __shared__ float Ws[32][33];   // [d][n]
    const int tid = threadIdx.x;
    const int ty  = tid >> 4, tx = tid & 15;
    const int k0  = blockIdx.y * 32;
    const int n0  = blockIdx.x * 32;

    const int lrow = tid >> 3;          // 0..31
    const int lc4  = (tid & 7) * 4;     // 0,4,..28

    float acc[2][2] = {};
    for (int kt = 0; kt < D_DIM; kt += 32) {
        {
            const float4 q = *reinterpret_cast<const float4*>(Wq + (size_t)(k0 + lrow) * D_DIM + kt + lc4);
            const float4 k = *reinterpret_cast<const float4*>(Wk + (size_t)(k0 + lrow) * D_DIM + kt + lc4);
            const float4 v = *reinterpret_cast<const float4*>(Wv + (size_t)(k0 + lrow) * D_DIM + kt + lc4);
            const float4 da = *reinterpret_cast<const float4*>(g_diag + kt + lc4);
            const float4 db = *reinterpret_cast<const float4*>(g_diag + D_DIM + kt + lc4);
            const float4 dc = *reinterpret_cast<const float4*>(g_diag + 2 * D_DIM + kt + lc4);
            Ms[lrow][lc4 + 0] = q.x * da.x + k.x * db.x + v.x * dc.x;
            Ms[lrow][lc4 + 1] = q.y * da.y + k.y * db.y + v.y * dc.y;
            Ms[lrow][lc4 + 2] = q.z * da.z + k.z * db.z + v.z * dc.z;
            Ms[lrow][lc4 + 3] = q.w * da.w + k.w * db.w + v.w * dc.w;
            const float4 o = *reinterpret_cast<const float4*>(Wo + (size_t)(kt + lrow) * D_DIM + n0 + lc4);
            Ws[lrow][lc4 + 0] = o.x; Ws[lrow][lc4 + 1] = o.y;
            Ws[lrow][lc4 + 2] = o.z; Ws[lrow][lc4 + 3] = o.w;
        }
        __syncthreads();
#pragma unroll
        for (int kk = 0; kk < 32; kk++) {
            const float a0 = Ms[ty][kk],      a1 = Ms[ty + 16][kk];
            const float b0 = Ws[kk][tx],      b1 = Ws[kk][tx + 16];
            acc[0][0] += a0 * b0; acc[0][1] += a0 * b1;
            acc[1][0] += a1 * b0; acc[1][1] += a1 * b1;
        }
        __syncthreads();
    }
#pragma unroll
    for (int i = 0; i < 2; i++) {
        const int k = k0 + ty + i * 16;
        const int j = k & 7;
        const int kp = (k & ~7) | (j < 4 ? 2 * j : 2 * (j - 4) + 1);
#pragma unroll
        for (int jj = 0; jj < 2; jj++) {
            const int n = n0 + tx + jj * 16;
            g_W[(size_t)n * D_DIM + kp] = __uint_as_float(f2tf32(acc[i][jj]));
        }
    }
}

// ---------------------------------------------------------------------------
// Main GEMM: out = x @ W_eff, tf32 mma.sync.
// BM=128, BN=112, BK=32, 3-stage cp.async, 256 threads (4m x 2n warps),
// warp tile 32x56. A stride 36 (scalar CF), B stride 40 (v2 CF).
// ---------------------------------------------------------------------------
__global__ void __launch_bounds__(256, 2) gemm_tf32_kernel(const float* __restrict__ x,
                                                           float* __restrict__ out) {
    extern __shared__ __align__(16) float smem[];

    const int tid   = threadIdx.x;
    const int wid   = tid >> 5;
    const int lane  = tid & 31;
    const int g     = lane >> 2;
    const int t     = lane & 3;
    const int warpM = wid & 3;
    const int warpN = wid >> 2;

    const int m0 = blockIdx.y * BM;
    const int n0 = blockIdx.x * BN;

    const uint32_t smem_base = smem_u32(smem);

    float acc[2][7][4];
#pragma unroll
    for (int i = 0; i < 2; i++)
#pragma unroll
        for (int j = 0; j < 7; j++)
#pragma unroll
            for (int q = 0; q < 4; q++) acc[i][j][q] = 0.f;

    auto load_stage = [&](int s, int kt) {
        const uint32_t aBase = smem_base + (uint32_t)(s * STG_F) * 4u;
        const uint32_t bBase = aBase + (uint32_t)AS_F * 4u;
#pragma unroll
        for (int j = 0; j < 4; j++) {
            const int id  = tid + j * 256;
            const int row = id >> 3;
            const int c   = id & 7;
            CP16(aBase + (uint32_t)(row * A_STRIDE + c * 4) * 4u,
                 x + (size_t)(m0 + row) * D_DIM + kt + c * 4);
        }
#pragma unroll
        for (int j = 0; j < 3; j++) {
            const int id  = tid + j * 256;
            const int row = id >> 3;
            const int c   = id & 7;
            CP16(bBase + (uint32_t)(row * B_STRIDE + c * 4) * 4u,
                 g_W + (size_t)(n0 + row) * D_DIM + kt + c * 4);
        }
        if (tid < 128) {
            const int id  = tid + 768;
            const int row = id >> 3;
            const int c   = id & 7;
            CP16(bBase + (uint32_t)(row * B_STRIDE + c * 4) * 4u,
                 g_W + (size_t)(n0 + row) * D_DIM + kt + c * 4);
        }
    };

    load_stage(0, 0);
    CP_COMMIT();
    load_stage(1, BK);
    CP_COMMIT();

    const int NIT = D_DIM / BK;   // 14
#pragma unroll 1
    for (int it = 0; it < NIT; it++) {
        CP_WAIT1();
        __syncthreads();

        if (it + 2 < NIT) load_stage((it + 2) % NSTG, (it + 2) * BK);
        CP_COMMIT();

        const float* As = smem + (it % NSTG) * STG_F;
        const float* Bs = As + AS_F;
        const float* Arow = As + (warpM * 32 + g) * A_STRIDE;
        const float* Brow = Bs + (warpN * 56 + g) * B_STRIDE;

#pragma unroll
        for (int kk = 0; kk < 4; kk++) {
            const int k0 = kk * 8;
            uint32_t af[2][4];
#pragma unroll
            for (int mi = 0; mi < 2; mi++) {
                const float* Ar = Arow + mi * 16 * A_STRIDE;
                af[mi][0] = f2tf32(Ar[k0 + t]);
                af[mi][1] = f2tf32(Ar[8 * A_STRIDE + k0 + t]);
                af[mi][2] = f2tf32(Ar[k0 + t + 4]);
                af[mi][3] = f2tf32(Ar[8 * A_STRIDE + k0 + t + 4]);
            }
#pragma unroll
            for (int ni = 0; ni < 7; ni++) {
                // permuted layout: logical (k0+t, k0+t+4) at floats (k0+2t, k0+2t+1)
                const float2 bv = *reinterpret_cast<const float2*>(
                    Brow + ni * 8 * B_STRIDE + k0 + 2 * t);
                const uint32_t b0 = __float_as_uint(bv.x);
                const uint32_t b1 = __float_as_uint(bv.y);
                mma_tf32(acc[0][ni], af[0], b0, b1);
                mma_tf32(acc[1][ni], af[1], b0, b1);
            }
        }
        __syncthreads();
    }

    // ---- epilogue
#pragma unroll
    for (int mi = 0; mi < 2; mi++) {
        const int r0 = m0 + warpM * 32 + mi * 16 + g;
#pragma unroll
        for (int ni = 0; ni < 7; ni++) {
            const int c0 = n0 + warpN * 56 + ni * 8 + 2 * t;
            float2 v0, v1;
            v0.x = acc[mi][ni][0]; v0.y = acc[mi][ni][1];
            v1.x = acc[mi][ni][2]; v1.y = acc[mi][ni][3];
            *reinterpret_cast<float2*>(out + (size_t)r0 * D_DIM + c0)       = v0;
            *reinterpret_cast<float2*>(out + (size_t)(r0 + 8) * D_DIM + c0) = v1;
        }
    }
}

// ---------------------------------------------------------------------------
extern "C" void kernel_launch(void* const* d_in, const int* in_sizes, int n_in,
                              void* d_out, int out_size) {
    const float* x  = (const float*)d_in[0];
    const float* Wq = (const float*)d_in[1];
    const float* Wk = (const float*)d_in[2];
    const float* Wv = (const float*)d_in[3];
    const float* Wo = (const float*)d_in[4];
    const float* A  = (const float*)d_in[5];
    const float* B  = (const float*)d_in[6];
    const float* C  = (const float*)d_in[7];

    cudaFuncSetAttribute(gemm_tf32_kernel, cudaFuncAttributeMaxDynamicSharedMemorySize,
                         SMEM_BYTES);

    diag_kernel<<<1, D_DIM>>>(A, B, C);
    weff_kernel<<<dim3(D_DIM / 32, D_DIM / 32), 256>>>(Wq, Wk, Wv, Wo);
    gemm_tf32_kernel<<<dim3(D_DIM / BN, MTOT / BM), 256, SMEM_BYTES>>>(x, (float*)d_out);
}

// round 7
// speedup vs baseline: 1.2208x; 1.0185x over previous
#include <cuda_runtime.h>
#include <cstdint>

#define D_DIM  448
#define MTOT   32768
#define BM     128
#define BN     112
#define BK     32
#define NSTG   3
#define A_STRIDE 36                        // conflict-free scalar frag LDS
#define B_STRIDE 40                        // conflict-free v2 frag LDS
#define AS_F   (BM * A_STRIDE)             // 4608
#define BS_F   (BN * B_STRIDE)             // 4480
#define STG_F  (AS_F + BS_F)               // 9088
#define SMEM_BYTES (NSTG * STG_F * 4)      // 109056 -> 2 CTAs/SM

// W_eff transposed [n][k_perm], tf32-rounded. perm in 8-block: j<4 ? 2j : 2(j-4)+1
__device__ __align__(16) float g_W[D_DIM * D_DIM];

// ---- helpers ----------------------------------------------------------------
__device__ __forceinline__ uint32_t smem_u32(const void* p) {
    uint32_t a;
    asm("{ .reg .u64 t; cvta.to.shared.u64 t, %1; cvt.u32.u64 %0, t; }" : "=r"(a) : "l"(p));
    return a;
}
__device__ __forceinline__ uint32_t f2tf32(float f) {
    uint32_t r;
    asm("cvt.rna.tf32.f32 %0, %1;" : "=r"(r) : "f"(f));
    return r;
}
__device__ __forceinline__ void mma_tf32(float* c, const uint32_t* a, uint32_t b0, uint32_t b1) {
    asm volatile(
        "mma.sync.aligned.m16n8k8.row.col.f32.tf32.tf32.f32 "
        "{%0,%1,%2,%3}, {%4,%5,%6,%7}, {%8,%9}, {%0,%1,%2,%3};"
        : "+f"(c[0]), "+f"(c[1]), "+f"(c[2]), "+f"(c[3])
        : "r"(a[0]), "r"(a[1]), "r"(a[2]), "r"(a[3]), "r"(b0), "r"(b1));
}
#define CP16(dst, src) \
    asm volatile("cp.async.cg.shared.global [%0], [%1], 16;" :: "r"(dst), "l"(src) : "memory")
#define CP_COMMIT() asm volatile("cp.async.commit_group;" ::: "memory")
#define CP_WAIT1()  asm volatile("cp.async.wait_group 1;" ::: "memory")

// ---------------------------------------------------------------------------
// Prep (fused): W_eff = (Wq*diagA + Wk*diagB + Wv*diagC) @ Wo,
// written transposed + k-permuted + tf32 into g_W.
// 32x32 tiles, grid (14,14), 256 threads, 2x2 per thread. Diagonals staged
// to smem per block (L2-resident after first wave).
// ---------------------------------------------------------------------------
__global__ void __launch_bounds__(256) weff_kernel(const float* __restrict__ Wq,
                                                   const float* __restrict__ Wk,
                                                   const float* __restrict__ Wv,
                                                   const float* __restrict__ Wo,
                                                   const float* __restrict__ A,
                                                   const float* __restrict__ Bm,
                                                   const float* __restrict__ C) {
    __shared__ float dg[3][D_DIM];
    __shared__ float Ms[32][33];   // [k-row][d]
    __shared__ float Ws[32][33];   // [d][n]
    const int tid = threadIdx.x;
    for (int i = tid; i < D_DIM; i += 256) {
        dg[0][i] = A[(size_t)i * D_DIM + i];
        dg[1][i] = Bm[(size_t)i * D_DIM + i];
        dg[2][i] = C[(size_t)i * D_DIM + i];
    }
    __syncthreads();

    const int ty = tid >> 4, tx = tid & 15;
    const int k0 = blockIdx.y * 32;
    const int n0 = blockIdx.x * 32;
    const int lrow = tid >> 3;          // 0..31
    const int lc4  = (tid & 7) * 4;     // 0,4,..28

    float acc[2][2] = {};
    for (int kt = 0; kt < D_DIM; kt += 32) {
        {
            const float4 q = *reinterpret_cast<const float4*>(Wq + (size_t)(k0 + lrow) * D_DIM + kt + lc4);
            const float4 k = *reinterpret_cast<const float4*>(Wk + (size_t)(k0 + lrow) * D_DIM + kt + lc4);
            const float4 v = *reinterpret_cast<const float4*>(Wv + (size_t)(k0 + lrow) * D_DIM + kt + lc4);
            const float4 da = *reinterpret_cast<const float4*>(&dg[0][kt + lc4]);
            const float4 db = *reinterpret_cast<const float4*>(&dg[1][kt + lc4]);
            const float4 dc = *reinterpret_cast<const float4*>(&dg[2][kt + lc4]);
            Ms[lrow][lc4 + 0] = q.x * da.x + k.x * db.x + v.x * dc.x;
            Ms[lrow][lc4 + 1] = q.y * da.y + k.y * db.y + v.y * dc.y;
            Ms[lrow][lc4 + 2] = q.z * da.z + k.z * db.z + v.z * dc.z;
            Ms[lrow][lc4 + 3] = q.w * da.w + k.w * db.w + v.w * dc.w;
            const float4 o = *reinterpret_cast<const float4*>(Wo + (size_t)(kt + lrow) * D_DIM + n0 + lc4);
            Ws[lrow][lc4 + 0] = o.x; Ws[lrow][lc4 + 1] = o.y;
            Ws[lrow][lc4 + 2] = o.z; Ws[lrow][lc4 + 3] = o.w;
        }
        __syncthreads();
#pragma unroll
        for (int kk = 0; kk < 32; kk++) {
            const float a0 = Ms[ty][kk],      a1 = Ms[ty + 16][kk];
            const float b0 = Ws[kk][tx],      b1 = Ws[kk][tx + 16];
            acc[0][0] += a0 * b0; acc[0][1] += a0 * b1;
            acc[1][0] += a1 * b0; acc[1][1] += a1 * b1;
        }
        __syncthreads();
    }
#pragma unroll
    for (int i = 0; i < 2; i++) {
        const int k = k0 + ty + i * 16;
        const int j = k & 7;
        const int kp = (k & ~7) | (j < 4 ? 2 * j : 2 * (j - 4) + 1);
#pragma unroll
        for (int jj = 0; jj < 2; jj++) {
            const int n = n0 + tx + jj * 16;
            g_W[(size_t)n * D_DIM + kp] = __uint_as_float(f2tf32(acc[i][jj]));
        }
    }
}

// ---------------------------------------------------------------------------
// Main GEMM: out = x @ W_eff, tf32 mma.sync.
// BM=128, BN=112, BK=32, 3-stage cp.async, 256 threads (4m x 2n warps),
// warp tile 32x56. ONE sync per mainloop iteration (safe with 3 stages:
// the top-of-iter sync proves all warps finished iter it-1, whose slot
// (it+2)%3 is the prefetch target).
// ---------------------------------------------------------------------------
__global__ void __launch_bounds__(256, 2) gemm_tf32_kernel(const float* __restrict__ x,
                                                           float* __restrict__ out) {
    extern __shared__ __align__(16) float smem[];

    const int tid   = threadIdx.x;
    const int wid   = tid >> 5;
    const int lane  = tid & 31;
    const int g     = lane >> 2;
    const int t     = lane & 3;
    const int warpM = wid & 3;
    const int warpN = wid >> 2;

    const int m0 = blockIdx.y * BM;
    const int n0 = blockIdx.x * BN;

    const uint32_t smem_base = smem_u32(smem);

    float acc[2][7][4];
#pragma unroll
    for (int i = 0; i < 2; i++)
#pragma unroll
        for (int j = 0; j < 7; j++)
#pragma unroll
            for (int q = 0; q < 4; q++) acc[i][j][q] = 0.f;

    auto load_stage = [&](int s, int kt) {
        const uint32_t aBase = smem_base + (uint32_t)(s * STG_F) * 4u;
        const uint32_t bBase = aBase + (uint32_t)AS_F * 4u;
#pragma unroll
        for (int j = 0; j < 4; j++) {
            const int id  = tid + j * 256;
            const int row = id >> 3;
            const int c   = id & 7;
            CP16(aBase + (uint32_t)(row * A_STRIDE + c * 4) * 4u,
                 x + (size_t)(m0 + row) * D_DIM + kt + c * 4);
        }
#pragma unroll
        for (int j = 0; j < 3; j++) {
            const int id  = tid + j * 256;
            const int row = id >> 3;
            const int c   = id & 7;
            CP16(bBase + (uint32_t)(row * B_STRIDE + c * 4) * 4u,
                 g_W + (size_t)(n0 + row) * D_DIM + kt + c * 4);
        }
        if (tid < 128) {
            const int id  = tid + 768;
            const int row = id >> 3;
            const int c   = id & 7;
            CP16(bBase + (uint32_t)(row * B_STRIDE + c * 4) * 4u,
                 g_W + (size_t)(n0 + row) * D_DIM + kt + c * 4);
        }
    };

    load_stage(0, 0);
    CP_COMMIT();
    load_stage(1, BK);
    CP_COMMIT();

    const int NIT = D_DIM / BK;   // 14
#pragma unroll 1
    for (int it = 0; it < NIT; it++) {
        CP_WAIT1();
        __syncthreads();

        if (it + 2 < NIT) load_stage((it + 2) % NSTG, (it + 2) * BK);
        CP_COMMIT();

        const float* As = smem + (it % NSTG) * STG_F;
        const float* Bs = As + AS_F;
        const float* Arow = As + (warpM * 32 + g) * A_STRIDE;
        const float* Brow = Bs + (warpN * 56 + g) * B_STRIDE;

#pragma unroll
        for (int kk = 0; kk < 4; kk++) {
            const int k0 = kk * 8;
            uint32_t af[2][4];
#pragma unroll
            for (int mi = 0; mi < 2; mi++) {
                const float* Ar = Arow + mi * 16 * A_STRIDE;
                af[mi][0] = f2tf32(Ar[k0 + t]);
                af[mi][1] = f2tf32(Ar[8 * A_STRIDE + k0 + t]);
                af[mi][2] = f2tf32(Ar[k0 + t + 4]);
                af[mi][3] = f2tf32(Ar[8 * A_STRIDE + k0 + t + 4]);
            }
#pragma unroll
            for (int ni = 0; ni < 7; ni++) {
                const float2 bv = *reinterpret_cast<const float2*>(
                    Brow + ni * 8 * B_STRIDE + k0 + 2 * t);
                const uint32_t b0 = __float_as_uint(bv.x);
                const uint32_t b1 = __float_as_uint(bv.y);
                mma_tf32(acc[0][ni], af[0], b0, b1);
                mma_tf32(acc[1][ni], af[1], b0, b1);
            }
        }
        // no trailing sync: top-of-iter sync of iter it+1 provides the ordering
    }

    // ---- epilogue
#pragma unroll
    for (int mi = 0; mi < 2; mi++) {
        const int r0 = m0 + warpM * 32 + mi * 16 + g;
#pragma unroll
        for (int ni = 0; ni < 7; ni++) {
            const int c0 = n0 + warpN * 56 + ni * 8 + 2 * t;
            float2 v0, v1;
            v0.x = acc[mi][ni][0]; v0.y = acc[mi][ni][1];
            v1.x = acc[mi][ni][2]; v1.y = acc[mi][ni][3];
            *reinterpret_cast<float2*>(out + (size_t)r0 * D_DIM + c0)       = v0;
            *reinterpret_cast<float2*>(out + (size_t)(r0 + 8) * D_DIM + c0) = v1;
        }
    }
}

// ---------------------------------------------------------------------------
extern "C" void kernel_launch(void* const* d_in, const int* in_sizes, int n_in,
                              void* d_out, int out_size) {
    const float* x  = (const float*)d_in[0];
    const float* Wq = (const float*)d_in[1];
    const float* Wk = (const float*)d_in[2];
    const float* Wv = (const float*)d_in[3];
    const float* Wo = (const float*)d_in[4];
    const float* A  = (const float*)d_in[5];
    const float* B  = (const float*)d_in[6];
    const float* C  = (const float*)d_in[7];

    cudaFuncSetAttribute(gemm_tf32_kernel, cudaFuncAttributeMaxDynamicSharedMemorySize,
                         SMEM_BYTES);

    weff_kernel<<<dim3(D_DIM / 32, D_DIM / 32), 256>>>(Wq, Wk, Wv, Wo, A, B, C);
    gemm_tf32_kernel<<<dim3(D_DIM / BN, MTOT / BM), 256, SMEM_BYTES>>>(x, (float*)d_out);
}